// round 6
// baseline (speedup 1.0000x reference)
#include <cuda_runtime.h>
#include <math.h>
#include <mma.h>

using namespace nvcuda;

// Problem constants
#define B_    256
#define P_    100
#define ENC_  1536
#define DEC_  512
#define ATT_  256
#define EMB_  256
#define V_    193
#define T_    150
#define T1_   151
#define N1_   1792   // att2(256) + f_beta(1536)
#define K2_   2048   // awe(1536) + h(512)
#define N2_   2048   // 4*DEC gate-interleaved

// Scratch (device globals: allocation-free per harness rules)
__device__ float g_h[B_ * DEC_];
__device__ float g_c[B_ * DEC_];
__device__ float g_mean[B_ * ENC_];
__device__ float g_att1[B_ * P_ * ATT_];
__device__ float g_hproj[B_ * N1_];
__device__ float g_x[B_ * K2_];          // [gated awe (1536) | h (512)]
__device__ float g_alpha[B_ * P_];
__device__ float g_Wcat1[DEC_ * N1_];    // [W_dec_att | W_f_beta]
__device__ float g_bcat1[N1_];
__device__ float g_Wcat2[K2_ * N2_];     // rows: [W_ih_enc ; W_hh], cols interleaved d*4+g
__device__ float g_embW[V_ * N2_];       // emb@W_ih_emb + b_ih + b_hh, cols interleaved

// Grid barrier state (zero-initialized at module load; count self-resets each
// generation, flag is monotonic -> consistent across graph replays)
__device__ volatile unsigned g_bar_flag;
__device__ unsigned g_bar_count;

__device__ __forceinline__ float sigmoidf_(float x) { return 1.0f / (1.0f + expf(-x)); }

__device__ __forceinline__ float tf32r(float x) {
    unsigned int u = __float_as_uint(x), v;
    asm("cvt.rna.tf32.f32 %0, %1;" : "=r"(v) : "r"(u));
    return __uint_as_float(v);
}
__device__ __forceinline__ float4 tf32r4(float4 v) {
    return make_float4(tf32r(v.x), tf32r(v.y), tf32r(v.z), tf32r(v.w));
}

typedef wmma::fragment<wmma::matrix_a, 16, 16, 8, wmma::precision::tf32, wmma::row_major> FragA;
typedef wmma::fragment<wmma::matrix_b, 16, 16, 8, wmma::precision::tf32, wmma::row_major> FragB;
typedef wmma::fragment<wmma::accumulator, 16, 16, 8, float> FragC;

// Shared-memory union for the persistent kernel phases
struct SmemT {
    union {
        struct { float As[32][36]; float Bs[32][136]; } gemm;   // 22016 B
        struct { float att2s[ATT_]; float wf[ATT_]; float es[P_ + 4]; } attn;
        float hs[DEC_];
        float al[128];
    } u;
};

// ---------------------------------------------------------------------------
// Grid-wide barrier. Safe single-counter sense-reversing pattern:
// a block can only reach barrier k+1 after barrier k releases (all nb arrived),
// and the releaser resets count BEFORE bumping flag (fence-ordered), so counts
// never mix across generations.
// ---------------------------------------------------------------------------
__device__ __forceinline__ void grid_sync_() {
    __syncthreads();
    if (threadIdx.x == 0) {
        __threadfence();
        unsigned gen = g_bar_flag;
        if (atomicAdd(&g_bar_count, 1) == gridDim.x - 1) {
            g_bar_count = 0;
            __threadfence();
            g_bar_flag = gen + 1;
        } else {
            while (g_bar_flag == gen) { __nanosleep(64); }
            __threadfence();
        }
    }
    __syncthreads();
}

// ---------------------------------------------------------------------------
// tf32 tensor-core 32x128 GEMM tile, BK=32, 256 threads = 8 warps (2 M x 4 N).
// ---------------------------------------------------------------------------
__device__ __forceinline__ void gemm_tc_tile(const float* __restrict__ A, int lda,
                                             const float* __restrict__ W, int N, int K,
                                             int rows0, int cols0,
                                             float (*As)[36], float (*Bs)[136],
                                             FragC& acc0, FragC& acc1,
                                             int warpM, int warpN) {
    const int tid  = threadIdx.x;
    const int arow = tid >> 3;           // 0..31
    const int acol = (tid & 7) << 2;     // 0..28
    const int brow = tid >> 5;           // 0..7 (+8r)
    const int bcol = (tid & 31) << 2;    // 0..124

    float4 aReg = *(const float4*)(A + (size_t)(rows0 + arow) * lda + acol);
    float4 bReg[4];
#pragma unroll
    for (int r = 0; r < 4; r++)
        bReg[r] = *(const float4*)(W + (size_t)(brow + 8 * r) * N + cols0 + bcol);

    for (int k0 = 0; k0 < K; k0 += 32) {
        *(float4*)&As[arow][acol] = tf32r4(aReg);
#pragma unroll
        for (int r = 0; r < 4; r++)
            *(float4*)&Bs[brow + 8 * r][bcol] = tf32r4(bReg[r]);
        __syncthreads();
        if (k0 + 32 < K) {
            aReg = *(const float4*)(A + (size_t)(rows0 + arow) * lda + k0 + 32 + acol);
#pragma unroll
            for (int r = 0; r < 4; r++)
                bReg[r] = *(const float4*)(W + (size_t)(k0 + 32 + brow + 8 * r) * N + cols0 + bcol);
        }
#pragma unroll
        for (int ks = 0; ks < 4; ks++) {
            FragA af;
            FragB bf0, bf1;
            wmma::load_matrix_sync(af, &As[warpM * 16][ks * 8], 36);
            wmma::load_matrix_sync(bf0, &Bs[ks * 8][warpN * 32], 136);
            wmma::load_matrix_sync(bf1, &Bs[ks * 8][warpN * 32 + 16], 136);
            wmma::mma_sync(acc0, af, bf0, acc0);
            wmma::mma_sync(acc1, af, bf1, acc1);
        }
        __syncthreads();
    }
}

// ---------------------------------------------------------------------------
// Persistent-kernel phase units
// ---------------------------------------------------------------------------

// hproj tile: hproj[rows0:+32, cols0:+128] = h @ Wcat1 + bcat1
__device__ void unit_hproj(SmemT& sm, const float* h, const float* Wcat1,
                           const float* bcat1, float* hproj,
                           const int* len, int t, int u) {
    const int rows0 = (u / 14) * 32;
    const int cols0 = (u % 14) * 128;
    if (t >= len[rows0] - 1) return;
    const int warp = threadIdx.x >> 5;
    const int warpM = warp >> 2, warpN = warp & 3;
    FragC acc0, acc1;
    wmma::fill_fragment(acc0, 0.0f);
    wmma::fill_fragment(acc1, 0.0f);
    gemm_tc_tile(h, DEC_, Wcat1, N1_, DEC_, rows0, cols0,
                 sm.u.gemm.As, sm.u.gemm.Bs, acc0, acc1, warpM, warpN);
    wmma::store_matrix_sync(&sm.u.gemm.Bs[warpM * 16][warpN * 32], acc0, 136, wmma::mem_row_major);
    wmma::store_matrix_sync(&sm.u.gemm.Bs[warpM * 16][warpN * 32 + 16], acc1, 136, wmma::mem_row_major);
    __syncthreads();
    const int tid = threadIdx.x;
    const int r = tid >> 3;
    const int cb = (tid & 7) << 4;
#pragma unroll
    for (int uu = 0; uu < 4; uu++) {
        const int col = cb + uu * 4;
        float4 v = *(const float4*)&sm.u.gemm.Bs[r][col];
        float4 bv = *(const float4*)(bcat1 + cols0 + col);
        v.x += bv.x; v.y += bv.y; v.z += bv.z; v.w += bv.w;
        *(float4*)(hproj + (size_t)(rows0 + r) * N1_ + cols0 + col) = v;
    }
}

// preds for batch b at timestep tp
__device__ void unit_preds(SmemT& sm, const float* Wfc, const float* bfc,
                           const float* h, float* out,
                           const int* len, int tp, int b) {
    const int tid = threadIdx.x;
    float* o = out + ((size_t)b * T_ + tp) * V_;
    if (tp >= len[b] - 1) {
        if (tid < V_) o[tid] = 0.0f;
        return;
    }
    sm.u.hs[tid] = h[(size_t)b * DEC_ + tid];
    sm.u.hs[tid + 256] = h[(size_t)b * DEC_ + tid + 256];
    __syncthreads();
    if (tid < V_) {
        float acc = bfc[tid];
#pragma unroll 8
        for (int k = 0; k < DEC_; k++) acc += sm.u.hs[k] * Wfc[(size_t)k * V_ + tid];
        o[tid] = acc;
    }
}

// scores + softmax for batch b; also copies h into x's recurrent slice
__device__ void unit_attn(SmemT& sm, const float* att1, const float* Wfull,
                          const float* hproj, const float* h,
                          float* alpha, float* x, const int* len, int t, int b) {
    if (t >= len[b] - 1) return;
    const int tid = threadIdx.x;
    const int warp = tid >> 5, lane = tid & 31;
    float* att2s = sm.u.attn.att2s;
    float* wf = sm.u.attn.wf;
    float* es = sm.u.attn.es;

    att2s[tid] = hproj[(size_t)b * N1_ + tid];
    wf[tid] = Wfull[tid];
    __syncthreads();

    for (int p = warp; p < P_; p += 8) {
        const float* a1 = att1 + ((size_t)(b * P_ + p)) * ATT_;
        float part = 0.0f;
#pragma unroll 4
        for (int j = lane; j < ATT_; j += 32)
            part += fmaxf(a1[j] + att2s[j], 0.0f) * wf[j];
#pragma unroll
        for (int o = 16; o; o >>= 1) part += __shfl_xor_sync(0xffffffffu, part, o);
        if (lane == 0) es[p] = part;
    }
    __syncthreads();

    if (tid < 32) {
        float m = -1e30f;
        for (int p = tid; p < P_; p += 32) m = fmaxf(m, es[p]);
#pragma unroll
        for (int o = 16; o; o >>= 1) m = fmaxf(m, __shfl_xor_sync(0xffffffffu, m, o));
        float s = 0.0f;
        for (int p = tid; p < P_; p += 32) {
            float ex = expf(es[p] - m);
            es[p] = ex;
            s += ex;
        }
#pragma unroll
        for (int o = 16; o; o >>= 1) s += __shfl_xor_sync(0xffffffffu, s, o);
        float inv = 1.0f / s;
        for (int p = tid; p < P_; p += 32) es[p] *= inv;
    }
    __syncthreads();

    if (tid < P_) alpha[b * P_ + tid] = es[tid];
    x[(size_t)b * K2_ + 1536 + tid] = h[(size_t)b * DEC_ + tid];
    x[(size_t)b * K2_ + 1536 + 256 + tid] = h[(size_t)b * DEC_ + 256 + tid];
}

// awe chunk: x[b, chunk] = sigmoid(gate) * sum_p alpha * enc. chunk = 768 floats.
__device__ void unit_awe(SmemT& sm, const float* enc, const float* alpha,
                         const float* hproj, float* x, const int* len, int t, int u) {
    const int b = u >> 1;
    if (t >= len[b] - 1) return;
    const int tid = threadIdx.x;
    const int c4 = (u & 1) * 192;   // float4 offset within ENC row

    if (tid < P_) sm.u.al[tid] = alpha[b * P_ + tid];
    __syncthreads();

    if (tid < 192) {
        const float4* ep = (const float4*)(enc + ((size_t)b * P_) * ENC_);
        float4 acc = make_float4(0.f, 0.f, 0.f, 0.f);
#pragma unroll 4
        for (int p = 0; p < P_; p++) {
            float4 v = ep[(size_t)p * (ENC_ / 4) + c4 + tid];
            float a = sm.u.al[p];
            acc.x += a * v.x; acc.y += a * v.y; acc.z += a * v.z; acc.w += a * v.w;
        }
        const int col = (c4 + tid) * 4;
        float4 gl = *(const float4*)(hproj + (size_t)b * N1_ + ATT_ + col);
        float4 o;
        o.x = acc.x * sigmoidf_(gl.x);
        o.y = acc.y * sigmoidf_(gl.y);
        o.z = acc.z * sigmoidf_(gl.z);
        o.w = acc.w * sigmoidf_(gl.w);
        *(float4*)(x + (size_t)b * K2_ + col) = o;
    }
}

// gates tile + fused LSTM cell
__device__ void unit_gates(SmemT& sm, const float* x, const float* W,
                           const float* embW, const int* caps,
                           float* h, float* c, const int* len, int t, int u) {
    const int rows0 = (u / 16) * 32;
    const int cols0 = (u % 16) * 128;
    if (t >= len[rows0] - 1) return;
    const int warp = threadIdx.x >> 5;
    const int warpM = warp >> 2, warpN = warp & 3;
    FragC acc0, acc1;
    wmma::fill_fragment(acc0, 0.0f);
    wmma::fill_fragment(acc1, 0.0f);
    gemm_tc_tile(x, K2_, W, N2_, K2_, rows0, cols0,
                 sm.u.gemm.As, sm.u.gemm.Bs, acc0, acc1, warpM, warpN);
    wmma::store_matrix_sync(&sm.u.gemm.Bs[warpM * 16][warpN * 32], acc0, 136, wmma::mem_row_major);
    wmma::store_matrix_sync(&sm.u.gemm.Bs[warpM * 16][warpN * 32 + 16], acc1, 136, wmma::mem_row_major);
    __syncthreads();

    const int tid = threadIdx.x;
    const int r = tid >> 3;
    const int cb = (tid & 7) << 4;
    const int b = rows0 + r;
    if (t >= len[b] - 1) return;
    const int token = caps[b * T1_ + t];

#pragma unroll
    for (int uu = 0; uu < 4; uu++) {
        const int cp = cols0 + cb + uu * 4;
        const int d = cp >> 2;
        float4 gv = *(const float4*)&sm.u.gemm.Bs[r][cb + uu * 4];
        float4 ew = *(const float4*)(embW + (size_t)token * N2_ + cp);
        float vi = gv.x + ew.x;
        float vf = gv.y + ew.y;
        float vg = gv.z + ew.z;
        float vo = gv.w + ew.w;
        float c_old = c[(size_t)b * DEC_ + d];
        float ii = sigmoidf_(vi);
        float ff = sigmoidf_(vf);
        float gg = tanhf(vg);
        float oo = sigmoidf_(vo);
        float cn = ff * c_old + ii * gg;
        float hn = oo * tanhf(cn);
        c[(size_t)b * DEC_ + d] = cn;
        h[(size_t)b * DEC_ + d] = hn;
    }
}

// ---------------------------------------------------------------------------
// Persistent kernel: all 150 timesteps with 4 grid barriers per step.
// ---------------------------------------------------------------------------
__global__ void __launch_bounds__(256)
persist_kernel(const float* __restrict__ enc, const int* __restrict__ caps,
               const int* __restrict__ len,
               const float* __restrict__ Wfull, const float* __restrict__ Wfc,
               const float* __restrict__ bfc,
               const float* __restrict__ att1, float* __restrict__ hproj,
               float* __restrict__ x, float* __restrict__ alpha,
               const float* __restrict__ Wcat1, const float* __restrict__ bcat1,
               const float* __restrict__ Wcat2, const float* __restrict__ embW,
               float* __restrict__ h, float* __restrict__ c,
               float* __restrict__ out) {
    __shared__ SmemT sm;
    const unsigned nb = gridDim.x;

    for (int t = 0; t < T_; t++) {
        // P1: hproj tiles (112) + preds for t-1 (256)
        for (unsigned u = blockIdx.x; u < 112u + 256u; u += nb) {
            if (u < 112u) {
                unit_hproj(sm, h, Wcat1, bcat1, hproj, len, t, (int)u);
            } else if (t > 0) {
                unit_preds(sm, Wfc, bfc, h, out, len, t - 1, (int)(u - 112u));
            }
            __syncthreads();
        }
        grid_sync_();

        // P2: attention scores + softmax (256)
        for (unsigned u = blockIdx.x; u < 256u; u += nb) {
            unit_attn(sm, att1, Wfull, hproj, h, alpha, x, len, t, (int)u);
            __syncthreads();
        }
        grid_sync_();

        // P3: awe (512)
        for (unsigned u = blockIdx.x; u < 512u; u += nb) {
            unit_awe(sm, enc, alpha, hproj, x, len, t, (int)u);
            __syncthreads();
        }
        grid_sync_();

        // P4: gates + LSTM cell (128)
        for (unsigned u = blockIdx.x; u < 128u; u += nb) {
            unit_gates(sm, x, Wcat2, embW, caps, h, c, len, t, (int)u);
            __syncthreads();
        }
        grid_sync_();
    }

    // final preds flush for t = T-1
    for (unsigned u = blockIdx.x; u < 256u; u += nb) {
        unit_preds(sm, Wfc, bfc, h, out, len, T_ - 1, (int)u);
        __syncthreads();
    }
}

// ---------------------------------------------------------------------------
// Standalone tf32 GEMM for precompute (h0, c0, att1)
// ---------------------------------------------------------------------------
__global__ void __launch_bounds__(256)
gemm_tc(const float* __restrict__ A, int lda,
        const float* __restrict__ W, int N, int K,
        const float* __restrict__ bias, float* __restrict__ C) {
    __shared__ __align__(16) float As[32][36];
    __shared__ __align__(16) float Bs[32][136];
    const int rows0 = blockIdx.y * 32;
    const int cols0 = blockIdx.x * 128;
    const int warp = threadIdx.x >> 5;
    const int warpM = warp >> 2, warpN = warp & 3;

    FragC acc0, acc1;
    wmma::fill_fragment(acc0, 0.0f);
    wmma::fill_fragment(acc1, 0.0f);
    gemm_tc_tile(A, lda, W, N, K, rows0, cols0, As, Bs, acc0, acc1, warpM, warpN);

    wmma::store_matrix_sync(&Bs[warpM * 16][warpN * 32], acc0, 136, wmma::mem_row_major);
    wmma::store_matrix_sync(&Bs[warpM * 16][warpN * 32 + 16], acc1, 136, wmma::mem_row_major);
    __syncthreads();

    const int tid = threadIdx.x;
    const int r = tid >> 3;
    const int cb = (tid & 7) << 4;
#pragma unroll
    for (int u = 0; u < 4; u++) {
        const int col = cb + u * 4;
        float4 v = *(const float4*)&Bs[r][col];
        float4 bv = *(const float4*)(bias + cols0 + col);
        v.x += bv.x; v.y += bv.y; v.z += bv.z; v.w += bv.w;
        *(float4*)(C + (size_t)(rows0 + r) * N + cols0 + col) = v;
    }
}

// ---------------------------------------------------------------------------
// Precompute kernels
// ---------------------------------------------------------------------------
__global__ void mean_kernel(const float* __restrict__ enc, float* __restrict__ mean) {
    const int b = blockIdx.y;
    const int e = blockIdx.x * 256 + threadIdx.x;
    const float* ep = enc + ((size_t)b * P_) * ENC_ + e;
    float s = 0.0f;
#pragma unroll 4
    for (int p = 0; p < P_; p++) s += ep[(size_t)p * ENC_];
    mean[(size_t)b * ENC_ + e] = s * (1.0f / P_);
}

__global__ void wcat1_kernel(const float* __restrict__ Wda, const float* __restrict__ Wfb,
                             const float* __restrict__ bda, const float* __restrict__ bfb,
                             float* __restrict__ Wc, float* __restrict__ bc) {
    int idx = blockIdx.x * 256 + threadIdx.x;
    if (idx >= DEC_ * N1_) return;
    int k = idx / N1_, n = idx % N1_;
    Wc[idx] = (n < ATT_) ? Wda[k * ATT_ + n] : Wfb[k * ENC_ + (n - ATT_)];
    if (k == 0) bc[n] = (n < ATT_) ? bda[n] : bfb[n - ATT_];
}

__global__ void wcat2_kernel(const float* __restrict__ Wih, const float* __restrict__ Whh,
                             float* __restrict__ Wc) {
    int idx = blockIdx.x * 256 + threadIdx.x;
    if (idx >= K2_ * N2_) return;
    int k = idx / N2_, cp = idx % N2_;
    int dd = cp >> 2, g = cp & 3;
    int oc = g * DEC_ + dd;
    Wc[idx] = (k < 1536) ? Wih[(size_t)(256 + k) * N2_ + oc]
                         : Whh[(size_t)(k - 1536) * N2_ + oc];
}

// embW[v, d*4+g] = sum_k emb[v,k] * W_ih[k, g*512+d] + b_ih + b_hh
// grid (8, 25): 8 rows of emb cached per block, 256 output cols per block.
__global__ void embw_kernel(const float* __restrict__ emb, const float* __restrict__ Wih,
                            const float* __restrict__ bih, const float* __restrict__ bhh,
                            float* __restrict__ out) {
    const int oc = blockIdx.x * 256 + threadIdx.x;   // 0..2047
    const int v0 = blockIdx.y * 8;
    __shared__ float er[8][EMB_];
#pragma unroll
    for (int r = 0; r < 8; r++) {
        int v = v0 + r;
        er[r][threadIdx.x] = (v < V_) ? emb[(size_t)v * EMB_ + threadIdx.x] : 0.0f;
    }
    __syncthreads();
    float base = bih[oc] + bhh[oc];
    float acc[8];
#pragma unroll
    for (int r = 0; r < 8; r++) acc[r] = base;
    for (int k = 0; k < EMB_; k++) {
        float w = Wih[(size_t)k * N2_ + oc];
#pragma unroll
        for (int r = 0; r < 8; r++) acc[r] += er[r][k] * w;
    }
    const int dd = oc & (DEC_ - 1);
    const int g = oc >> 9;
#pragma unroll
    for (int r = 0; r < 8; r++) {
        int v = v0 + r;
        if (v < V_) out[(size_t)v * N2_ + dd * 4 + g] = acc[r];
    }
}

// ---------------------------------------------------------------------------
extern "C" void kernel_launch(void* const* d_in, const int* in_sizes, int n_in,
                              void* d_out, int out_size) {
    const float* enc        = (const float*)d_in[0];
    const int*   caps       = (const int*)d_in[1];
    const int*   lens       = (const int*)d_in[2];
    const float* emb        = (const float*)d_in[3];
    const float* W_enc_att  = (const float*)d_in[4];
    const float* b_enc_att  = (const float*)d_in[5];
    const float* W_dec_att  = (const float*)d_in[6];
    const float* b_dec_att  = (const float*)d_in[7];
    const float* W_full_att = (const float*)d_in[8];
    // d_in[9] = b_full_att (softmax-invariant; unused)
    const float* W_init_h   = (const float*)d_in[10];
    const float* b_init_h   = (const float*)d_in[11];
    const float* W_init_c   = (const float*)d_in[12];
    const float* b_init_c   = (const float*)d_in[13];
    const float* W_f_beta   = (const float*)d_in[14];
    const float* b_f_beta   = (const float*)d_in[15];
    const float* W_ih       = (const float*)d_in[16];
    const float* b_ih       = (const float*)d_in[17];
    const float* W_hh       = (const float*)d_in[18];
    const float* b_hh       = (const float*)d_in[19];
    const float* W_fc       = (const float*)d_in[20];
    const float* b_fc       = (const float*)d_in[21];
    float* out = (float*)d_out;

    float *ph, *pc, *pmean, *patt1, *phproj, *px, *palpha, *pWcat1, *pbcat1, *pWcat2, *pembW;
    cudaGetSymbolAddress((void**)&ph,     g_h);
    cudaGetSymbolAddress((void**)&pc,     g_c);
    cudaGetSymbolAddress((void**)&pmean,  g_mean);
    cudaGetSymbolAddress((void**)&patt1,  g_att1);
    cudaGetSymbolAddress((void**)&phproj, g_hproj);
    cudaGetSymbolAddress((void**)&px,     g_x);
    cudaGetSymbolAddress((void**)&palpha, g_alpha);
    cudaGetSymbolAddress((void**)&pWcat1, g_Wcat1);
    cudaGetSymbolAddress((void**)&pbcat1, g_bcat1);
    cudaGetSymbolAddress((void**)&pWcat2, g_Wcat2);
    cudaGetSymbolAddress((void**)&pembW,  g_embW);

    int dev = 0;
    cudaGetDevice(&dev);
    int sms = 148;
    cudaDeviceGetAttribute(&sms, cudaDevAttrMultiProcessorCount, dev);

    // ---- precompute ----
    mean_kernel<<<dim3(ENC_ / 256, B_), 256>>>(enc, pmean);
    wcat1_kernel<<<(DEC_ * N1_ + 255) / 256, 256>>>(W_dec_att, W_f_beta, b_dec_att, b_f_beta,
                                                    pWcat1, pbcat1);
    wcat2_kernel<<<(K2_ * N2_ + 255) / 256, 256>>>(W_ih, W_hh, pWcat2);
    embw_kernel<<<dim3(N2_ / 256, (V_ + 7) / 8), 256>>>(emb, W_ih, b_ih, b_hh, pembW);
    // h0, c0
    gemm_tc<<<dim3(DEC_ / 128, B_ / 32), 256>>>(pmean, ENC_, W_init_h, DEC_, ENC_,
                                                b_init_h, ph);
    gemm_tc<<<dim3(DEC_ / 128, B_ / 32), 256>>>(pmean, ENC_, W_init_c, DEC_, ENC_,
                                                b_init_c, pc);
    // att1 = encoder_out @ W_enc_att + b (M = B*P = 25600)
    gemm_tc<<<dim3(ATT_ / 128, (B_ * P_) / 32), 256>>>(enc, ENC_, W_enc_att, ATT_, ENC_,
                                                       b_enc_att, patt1);

    // ---- all 150 timesteps in one persistent kernel ----
    persist_kernel<<<sms, 256>>>(enc, caps, lens, W_full_att, W_fc, b_fc,
                                 patt1, phproj, px, palpha,
                                 pWcat1, pbcat1, pWcat2, pembW,
                                 ph, pc, out);
}

// round 8
// speedup vs baseline: 1.3402x; 1.3402x over previous
#include <cuda_runtime.h>
#include <math.h>
#include <mma.h>

using namespace nvcuda;

// Problem constants
#define B_    256
#define P_    100
#define ENC_  1536
#define DEC_  512
#define ATT_  256
#define EMB_  256
#define V_    193
#define T_    150
#define T1_   151
#define N1_   1792   // att2(256) + f_beta(1536)
#define K2_   2048   // awe(1536) + h(512)
#define N2_   2048   // 4*DEC gate-interleaved

#define HP_BLOCKS 112          // hproj tiles in fused kernel 1
#define HPP_GRID (HP_BLOCKS + B_)

// Scratch (device globals: allocation-free per harness rules)
__device__ float g_h[B_ * DEC_];
__device__ float g_c[B_ * DEC_];
__device__ float g_mean[B_ * ENC_];
__device__ float g_att1[B_ * P_ * ATT_];
__device__ float g_hproj[B_ * N1_];
__device__ float g_x[B_ * K2_];          // [gated awe (1536) | h (512)]
__device__ float g_alpha[B_ * P_];
__device__ float g_Wcat1[DEC_ * N1_];    // [W_dec_att | W_f_beta]
__device__ float g_bcat1[N1_];
__device__ float g_Wcat2[K2_ * N2_];     // rows: [W_ih_enc ; W_hh], cols interleaved d*4+g
__device__ float g_embW[V_ * N2_];       // emb@W_ih_emb + b_ih + b_hh, cols interleaved

__device__ __forceinline__ float sigmoidf_(float x) { return 1.0f / (1.0f + expf(-x)); }

__device__ __forceinline__ float tf32r(float x) {
    unsigned int u = __float_as_uint(x), v;
    asm("cvt.rna.tf32.f32 %0, %1;" : "=r"(v) : "r"(u));
    return __uint_as_float(v);
}
__device__ __forceinline__ float4 tf32r4(float4 v) {
    return make_float4(tf32r(v.x), tf32r(v.y), tf32r(v.z), tf32r(v.w));
}

typedef wmma::fragment<wmma::matrix_a, 16, 16, 8, wmma::precision::tf32, wmma::row_major> FragA;
typedef wmma::fragment<wmma::matrix_b, 16, 16, 8, wmma::precision::tf32, wmma::row_major> FragB;
typedef wmma::fragment<wmma::accumulator, 16, 16, 8, float> FragC;

// ---------------------------------------------------------------------------
// tf32 tensor-core 32x128 GEMM tile, BK=32, 256 threads = 8 warps (2 M x 4 N).
// ---------------------------------------------------------------------------
__device__ __forceinline__ void gemm_tc_tile(const float* __restrict__ A, int lda,
                                             const float* __restrict__ W, int N, int K,
                                             int rows0, int cols0,
                                             float (*As)[36], float (*Bs)[136],
                                             FragC& acc0, FragC& acc1,
                                             int warpM, int warpN) {
    const int tid  = threadIdx.x;
    const int arow = tid >> 3;           // 0..31
    const int acol = (tid & 7) << 2;     // 0..28
    const int brow = tid >> 5;           // 0..7 (+8r)
    const int bcol = (tid & 31) << 2;    // 0..124

    float4 aReg = *(const float4*)(A + (size_t)(rows0 + arow) * lda + acol);
    float4 bReg[4];
#pragma unroll
    for (int r = 0; r < 4; r++)
        bReg[r] = *(const float4*)(W + (size_t)(brow + 8 * r) * N + cols0 + bcol);

    for (int k0 = 0; k0 < K; k0 += 32) {
        *(float4*)&As[arow][acol] = tf32r4(aReg);
#pragma unroll
        for (int r = 0; r < 4; r++)
            *(float4*)&Bs[brow + 8 * r][bcol] = tf32r4(bReg[r]);
        __syncthreads();
        if (k0 + 32 < K) {
            aReg = *(const float4*)(A + (size_t)(rows0 + arow) * lda + k0 + 32 + acol);
#pragma unroll
            for (int r = 0; r < 4; r++)
                bReg[r] = *(const float4*)(W + (size_t)(k0 + 32 + brow + 8 * r) * N + cols0 + bcol);
        }
#pragma unroll
        for (int ks = 0; ks < 4; ks++) {
            FragA af;
            FragB bf0, bf1;
            wmma::load_matrix_sync(af, &As[warpM * 16][ks * 8], 36);
            wmma::load_matrix_sync(bf0, &Bs[ks * 8][warpN * 32], 136);
            wmma::load_matrix_sync(bf1, &Bs[ks * 8][warpN * 32 + 16], 136);
            wmma::mma_sync(acc0, af, bf0, acc0);
            wmma::mma_sync(acc1, af, bf1, acc1);
        }
        __syncthreads();
    }
}

// ---------------------------------------------------------------------------
// Fused kernel 1: blocks 0..111 compute hproj tiles (h @ Wcat1 + bcat1);
// blocks 112..367 compute preds for timestep t-1 (skipped at t==0).
// Both only read h (state after gates of t-1) -> dependency-clean in one launch.
// ---------------------------------------------------------------------------
__global__ void __launch_bounds__(256)
hproj_preds(const float* __restrict__ h, const float* __restrict__ Wcat1,
            const float* __restrict__ bcat1, float* __restrict__ hproj,
            const float* __restrict__ Wfc, const float* __restrict__ bfc,
            float* __restrict__ out, const int* __restrict__ len, int t) {
    __shared__ __align__(16) float As[32][36];
    __shared__ __align__(16) float Bs[32][136];
    __shared__ float hs[DEC_];

    const int blk = blockIdx.x;
    const int tid = threadIdx.x;

    if (blk < HP_BLOCKS) {
        // ---- hproj GEMM tile ----
        const int rows0 = (blk / 14) * 32;
        const int cols0 = (blk % 14) * 128;
        if (t >= len[rows0] - 1) return;
        const int warp = tid >> 5;
        const int warpM = warp >> 2, warpN = warp & 3;
        FragC acc0, acc1;
        wmma::fill_fragment(acc0, 0.0f);
        wmma::fill_fragment(acc1, 0.0f);
        gemm_tc_tile(h, DEC_, Wcat1, N1_, DEC_, rows0, cols0, As, Bs,
                     acc0, acc1, warpM, warpN);
        wmma::store_matrix_sync(&Bs[warpM * 16][warpN * 32], acc0, 136, wmma::mem_row_major);
        wmma::store_matrix_sync(&Bs[warpM * 16][warpN * 32 + 16], acc1, 136, wmma::mem_row_major);
        __syncthreads();
        const int r = tid >> 3;
        const int cb = (tid & 7) << 4;
#pragma unroll
        for (int u = 0; u < 4; u++) {
            const int col = cb + u * 4;
            float4 v = *(const float4*)&Bs[r][col];
            float4 bv = *(const float4*)(bcat1 + cols0 + col);
            v.x += bv.x; v.y += bv.y; v.z += bv.z; v.w += bv.w;
            *(float4*)(hproj + (size_t)(rows0 + r) * N1_ + cols0 + col) = v;
        }
    } else {
        // ---- preds for t-1 ----
        if (t == 0) return;
        const int b = blk - HP_BLOCKS;
        const int tp = t - 1;
        float* o = out + ((size_t)b * T_ + tp) * V_;
        if (tp >= len[b] - 1) {
            if (tid < V_) o[tid] = 0.0f;
            return;
        }
        hs[tid] = h[(size_t)b * DEC_ + tid];
        hs[tid + 256] = h[(size_t)b * DEC_ + tid + 256];
        __syncthreads();
        if (tid < V_) {
            float acc = bfc[tid];
#pragma unroll 8
            for (int k = 0; k < DEC_; k++) acc += hs[k] * Wfc[(size_t)k * V_ + tid];
            o[tid] = acc;
        }
    }
}

// ---------------------------------------------------------------------------
// Scores + softmax (512 threads = 16 warps -> 7 p-rounds); also copies h into
// x's recurrent slice (one element per thread).
// ---------------------------------------------------------------------------
__global__ void __launch_bounds__(512)
attn_scores(const float* __restrict__ att1, const float* __restrict__ Wfull,
            const float* __restrict__ hproj, const float* __restrict__ h,
            float* __restrict__ alpha, float* __restrict__ x,
            const int* __restrict__ len, int t) {
    const int b = blockIdx.x;
    if (t >= len[b] - 1) return;
    const int tid = threadIdx.x;
    const int warp = tid >> 5, lane = tid & 31;

    __shared__ float att2s[ATT_];
    __shared__ float wf[ATT_];
    __shared__ float es[P_ + 4];

    if (tid < ATT_) {
        att2s[tid] = hproj[(size_t)b * N1_ + tid];
        wf[tid] = Wfull[tid];
    }
    __syncthreads();

    for (int p = warp; p < P_; p += 16) {
        const float* a1 = att1 + ((size_t)(b * P_ + p)) * ATT_;
        float part = 0.0f;
#pragma unroll 4
        for (int j = lane; j < ATT_; j += 32)
            part += fmaxf(a1[j] + att2s[j], 0.0f) * wf[j];
#pragma unroll
        for (int o = 16; o; o >>= 1) part += __shfl_xor_sync(0xffffffffu, part, o);
        if (lane == 0) es[p] = part;
    }
    __syncthreads();

    if (tid < 32) {
        float m = -1e30f;
        for (int p = tid; p < P_; p += 32) m = fmaxf(m, es[p]);
#pragma unroll
        for (int o = 16; o; o >>= 1) m = fmaxf(m, __shfl_xor_sync(0xffffffffu, m, o));
        float s = 0.0f;
        for (int p = tid; p < P_; p += 32) {
            float ex = expf(es[p] - m);
            es[p] = ex;
            s += ex;
        }
#pragma unroll
        for (int o = 16; o; o >>= 1) s += __shfl_xor_sync(0xffffffffu, s, o);
        float inv = 1.0f / s;
        for (int p = tid; p < P_; p += 32) es[p] *= inv;
    }
    __syncthreads();

    if (tid < P_) alpha[b * P_ + tid] = es[tid];
    // copy h into x's recurrent slice (512 threads -> one element each)
    x[(size_t)b * K2_ + 1536 + tid] = h[(size_t)b * DEC_ + tid];
}

// ---------------------------------------------------------------------------
// awe: x[b, chunk] = sigmoid(gate) * sum_p alpha[b,p] * enc[b,p,chunk].
// grid (3, B): each block handles a 512-float chunk of ENC with 128 threads.
// ---------------------------------------------------------------------------
__global__ void awe_kernel(const float* __restrict__ enc, const float* __restrict__ alpha,
                           const float* __restrict__ hproj, float* __restrict__ x,
                           const int* __restrict__ len, int t) {
    const int b = blockIdx.y;
    if (t >= len[b] - 1) return;
    const int tid = threadIdx.x;
    const int chunk0 = blockIdx.x * 512;        // float offset within ENC

    __shared__ float al[P_];
    if (tid < P_) al[tid] = alpha[b * P_ + tid];
    __syncthreads();

    const float4* ep = (const float4*)(enc + ((size_t)b * P_) * ENC_ + chunk0);
    float4 acc = make_float4(0.f, 0.f, 0.f, 0.f);
#pragma unroll 4
    for (int p = 0; p < P_; p++) {
        float4 v = ep[(size_t)p * (ENC_ / 4) + tid];
        float a = al[p];
        acc.x += a * v.x; acc.y += a * v.y; acc.z += a * v.z; acc.w += a * v.w;
    }
    const int col = chunk0 + tid * 4;
    float4 gl = *(const float4*)(hproj + (size_t)b * N1_ + ATT_ + col);
    float4 o;
    o.x = acc.x * sigmoidf_(gl.x);
    o.y = acc.y * sigmoidf_(gl.y);
    o.z = acc.z * sigmoidf_(gl.z);
    o.w = acc.w * sigmoidf_(gl.w);
    *(float4*)(x + (size_t)b * K2_ + col) = o;
}

// ---------------------------------------------------------------------------
// Fused gates GEMM (tf32) + LSTM cell.
// ---------------------------------------------------------------------------
__global__ void __launch_bounds__(256)
gates_tc(const float* __restrict__ x, const float* __restrict__ W,
         const float* __restrict__ embW, const int* __restrict__ caps,
         float* __restrict__ h, float* __restrict__ c,
         const int* __restrict__ len, int t) {
    __shared__ __align__(16) float As[32][36];
    __shared__ __align__(16) float Bs[32][136];
    const int rows0 = blockIdx.y * 32;
    if (t >= len[rows0] - 1) return;
    const int cols0 = blockIdx.x * 128;
    const int warp = threadIdx.x >> 5;
    const int warpM = warp >> 2, warpN = warp & 3;

    FragC acc0, acc1;
    wmma::fill_fragment(acc0, 0.0f);
    wmma::fill_fragment(acc1, 0.0f);
    gemm_tc_tile(x, K2_, W, N2_, K2_, rows0, cols0, As, Bs, acc0, acc1, warpM, warpN);

    wmma::store_matrix_sync(&Bs[warpM * 16][warpN * 32], acc0, 136, wmma::mem_row_major);
    wmma::store_matrix_sync(&Bs[warpM * 16][warpN * 32 + 16], acc1, 136, wmma::mem_row_major);
    __syncthreads();

    const int tid = threadIdx.x;
    const int r = tid >> 3;
    const int cb = (tid & 7) << 4;
    const int b = rows0 + r;
    if (t >= len[b] - 1) return;
    const int token = caps[b * T1_ + t];

#pragma unroll
    for (int uu = 0; uu < 4; uu++) {
        const int cp = cols0 + cb + uu * 4;
        const int d = cp >> 2;
        float4 gv = *(const float4*)&Bs[r][cb + uu * 4];
        float4 ew = *(const float4*)(embW + (size_t)token * N2_ + cp);
        float vi = gv.x + ew.x;
        float vf = gv.y + ew.y;
        float vg = gv.z + ew.z;
        float vo = gv.w + ew.w;
        float c_old = c[(size_t)b * DEC_ + d];
        float ii = sigmoidf_(vi);
        float ff = sigmoidf_(vf);
        float gg = tanhf(vg);
        float oo = sigmoidf_(vo);
        float cn = ff * c_old + ii * gg;
        float hn = oo * tanhf(cn);
        c[(size_t)b * DEC_ + d] = cn;
        h[(size_t)b * DEC_ + d] = hn;
    }
}

// ---------------------------------------------------------------------------
// preds[b,t,:] = active ? h[b,:] @ W_fc + b_fc : 0   (final-step flush)
// ---------------------------------------------------------------------------
__global__ void preds_kernel(const float* __restrict__ Wfc, const float* __restrict__ bfc,
                             const float* __restrict__ h, float* __restrict__ out,
                             const int* __restrict__ len, int t) {
    const int b = blockIdx.x;
    const int tid = threadIdx.x;
    float* o = out + ((size_t)b * T_ + t) * V_;
    if (t >= len[b] - 1) {
        if (tid < V_) o[tid] = 0.0f;
        return;
    }
    __shared__ float hs[DEC_];
    hs[tid] = h[(size_t)b * DEC_ + tid];
    hs[tid + 256] = h[(size_t)b * DEC_ + tid + 256];
    __syncthreads();
    if (tid < V_) {
        float acc = bfc[tid];
#pragma unroll 8
        for (int k = 0; k < DEC_; k++) acc += hs[k] * Wfc[(size_t)k * V_ + tid];
        o[tid] = acc;
    }
}

// ---------------------------------------------------------------------------
// Standalone tf32 GEMM for precompute (h0, c0, att1)
// ---------------------------------------------------------------------------
__global__ void __launch_bounds__(256)
gemm_tc(const float* __restrict__ A, int lda,
        const float* __restrict__ W, int N, int K,
        const float* __restrict__ bias, float* __restrict__ C) {
    __shared__ __align__(16) float As[32][36];
    __shared__ __align__(16) float Bs[32][136];
    const int rows0 = blockIdx.y * 32;
    const int cols0 = blockIdx.x * 128;
    const int warp = threadIdx.x >> 5;
    const int warpM = warp >> 2, warpN = warp & 3;

    FragC acc0, acc1;
    wmma::fill_fragment(acc0, 0.0f);
    wmma::fill_fragment(acc1, 0.0f);
    gemm_tc_tile(A, lda, W, N, K, rows0, cols0, As, Bs, acc0, acc1, warpM, warpN);

    wmma::store_matrix_sync(&Bs[warpM * 16][warpN * 32], acc0, 136, wmma::mem_row_major);
    wmma::store_matrix_sync(&Bs[warpM * 16][warpN * 32 + 16], acc1, 136, wmma::mem_row_major);
    __syncthreads();

    const int tid = threadIdx.x;
    const int r = tid >> 3;
    const int cb = (tid & 7) << 4;
#pragma unroll
    for (int u = 0; u < 4; u++) {
        const int col = cb + u * 4;
        float4 v = *(const float4*)&Bs[r][col];
        float4 bv = *(const float4*)(bias + cols0 + col);
        v.x += bv.x; v.y += bv.y; v.z += bv.z; v.w += bv.w;
        *(float4*)(C + (size_t)(rows0 + r) * N + cols0 + col) = v;
    }
}

// ---------------------------------------------------------------------------
// Precompute kernels
// ---------------------------------------------------------------------------
__global__ void mean_kernel(const float* __restrict__ enc, float* __restrict__ mean) {
    const int b = blockIdx.y;
    const int e = blockIdx.x * 256 + threadIdx.x;
    const float* ep = enc + ((size_t)b * P_) * ENC_ + e;
    float s = 0.0f;
#pragma unroll 4
    for (int p = 0; p < P_; p++) s += ep[(size_t)p * ENC_];
    mean[(size_t)b * ENC_ + e] = s * (1.0f / P_);
}

__global__ void wcat1_kernel(const float* __restrict__ Wda, const float* __restrict__ Wfb,
                             const float* __restrict__ bda, const float* __restrict__ bfb,
                             float* __restrict__ Wc, float* __restrict__ bc) {
    int idx = blockIdx.x * 256 + threadIdx.x;
    if (idx >= DEC_ * N1_) return;
    int k = idx / N1_, n = idx % N1_;
    Wc[idx] = (n < ATT_) ? Wda[k * ATT_ + n] : Wfb[k * ENC_ + (n - ATT_)];
    if (k == 0) bc[n] = (n < ATT_) ? bda[n] : bfb[n - ATT_];
}

__global__ void wcat2_kernel(const float* __restrict__ Wih, const float* __restrict__ Whh,
                             float* __restrict__ Wc) {
    int idx = blockIdx.x * 256 + threadIdx.x;
    if (idx >= K2_ * N2_) return;
    int k = idx / N2_, cp = idx % N2_;
    int dd = cp >> 2, g = cp & 3;
    int oc = g * DEC_ + dd;
    Wc[idx] = (k < 1536) ? Wih[(size_t)(256 + k) * N2_ + oc]
                         : Whh[(size_t)(k - 1536) * N2_ + oc];
}

// embW[v, d*4+g] = sum_k emb[v,k] * W_ih[k, g*512+d] + b_ih + b_hh
__global__ void embw_kernel(const float* __restrict__ emb, const float* __restrict__ Wih,
                            const float* __restrict__ bih, const float* __restrict__ bhh,
                            float* __restrict__ out) {
    const int oc = blockIdx.x * 256 + threadIdx.x;   // 0..2047
    const int v0 = blockIdx.y * 8;
    __shared__ float er[8][EMB_];
#pragma unroll
    for (int r = 0; r < 8; r++) {
        int v = v0 + r;
        er[r][threadIdx.x] = (v < V_) ? emb[(size_t)v * EMB_ + threadIdx.x] : 0.0f;
    }
    __syncthreads();
    float base = bih[oc] + bhh[oc];
    float acc[8];
#pragma unroll
    for (int r = 0; r < 8; r++) acc[r] = base;
    for (int k = 0; k < EMB_; k++) {
        float w = Wih[(size_t)k * N2_ + oc];
#pragma unroll
        for (int r = 0; r < 8; r++) acc[r] += er[r][k] * w;
    }
    const int dd = oc & (DEC_ - 1);
    const int g = oc >> 9;
#pragma unroll
    for (int r = 0; r < 8; r++) {
        int v = v0 + r;
        if (v < V_) out[(size_t)v * N2_ + dd * 4 + g] = acc[r];
    }
}

// ---------------------------------------------------------------------------
extern "C" void kernel_launch(void* const* d_in, const int* in_sizes, int n_in,
                              void* d_out, int out_size) {
    const float* enc        = (const float*)d_in[0];
    const int*   caps       = (const int*)d_in[1];
    const int*   lens       = (const int*)d_in[2];
    const float* emb        = (const float*)d_in[3];
    const float* W_enc_att  = (const float*)d_in[4];
    const float* b_enc_att  = (const float*)d_in[5];
    const float* W_dec_att  = (const float*)d_in[6];
    const float* b_dec_att  = (const float*)d_in[7];
    const float* W_full_att = (const float*)d_in[8];
    // d_in[9] = b_full_att (softmax-invariant; unused)
    const float* W_init_h   = (const float*)d_in[10];
    const float* b_init_h   = (const float*)d_in[11];
    const float* W_init_c   = (const float*)d_in[12];
    const float* b_init_c   = (const float*)d_in[13];
    const float* W_f_beta   = (const float*)d_in[14];
    const float* b_f_beta   = (const float*)d_in[15];
    const float* W_ih       = (const float*)d_in[16];
    const float* b_ih       = (const float*)d_in[17];
    const float* W_hh       = (const float*)d_in[18];
    const float* b_hh       = (const float*)d_in[19];
    const float* W_fc       = (const float*)d_in[20];
    const float* b_fc       = (const float*)d_in[21];
    float* out = (float*)d_out;

    float *ph, *pc, *pmean, *patt1, *phproj, *px, *palpha, *pWcat1, *pbcat1, *pWcat2, *pembW;
    cudaGetSymbolAddress((void**)&ph,     g_h);
    cudaGetSymbolAddress((void**)&pc,     g_c);
    cudaGetSymbolAddress((void**)&pmean,  g_mean);
    cudaGetSymbolAddress((void**)&patt1,  g_att1);
    cudaGetSymbolAddress((void**)&phproj, g_hproj);
    cudaGetSymbolAddress((void**)&px,     g_x);
    cudaGetSymbolAddress((void**)&palpha, g_alpha);
    cudaGetSymbolAddress((void**)&pWcat1, g_Wcat1);
    cudaGetSymbolAddress((void**)&pbcat1, g_bcat1);
    cudaGetSymbolAddress((void**)&pWcat2, g_Wcat2);
    cudaGetSymbolAddress((void**)&pembW,  g_embW);

    // ---- precompute ----
    mean_kernel<<<dim3(ENC_ / 256, B_), 256>>>(enc, pmean);
    wcat1_kernel<<<(DEC_ * N1_ + 255) / 256, 256>>>(W_dec_att, W_f_beta, b_dec_att, b_f_beta,
                                                    pWcat1, pbcat1);
    wcat2_kernel<<<(K2_ * N2_ + 255) / 256, 256>>>(W_ih, W_hh, pWcat2);
    embw_kernel<<<dim3(N2_ / 256, (V_ + 7) / 8), 256>>>(emb, W_ih, b_ih, b_hh, pembW);
    // h0, c0
    gemm_tc<<<dim3(DEC_ / 128, B_ / 32), 256>>>(pmean, ENC_, W_init_h, DEC_, ENC_,
                                                b_init_h, ph);
    gemm_tc<<<dim3(DEC_ / 128, B_ / 32), 256>>>(pmean, ENC_, W_init_c, DEC_, ENC_,
                                                b_init_c, pc);
    // att1 = encoder_out @ W_enc_att + b (M = B*P = 25600)
    gemm_tc<<<dim3(ATT_ / 128, (B_ * P_) / 32), 256>>>(enc, ENC_, W_enc_att, ATT_, ENC_,
                                                       b_enc_att, patt1);

    // ---- timestep loop: 4 launches/step ----
    for (int t = 0; t < T_; t++) {
        hproj_preds<<<HPP_GRID, 256>>>(ph, pWcat1, pbcat1, phproj, W_fc, b_fc, out, lens, t);
        attn_scores<<<B_, 512>>>(patt1, W_full_att, phproj, ph, palpha, px, lens, t);
        awe_kernel<<<dim3(3, B_), 128>>>(enc, palpha, phproj, px, lens, t);
        gates_tc<<<dim3(N2_ / 128, B_ / 32), 256>>>(px, pWcat2, pembW, caps, ph, pc,
                                                    lens, t);
    }
    // final preds flush
    preds_kernel<<<B_, 256>>>(W_fc, b_fc, ph, out, lens, T_ - 1);
}

// round 9
// speedup vs baseline: 1.3492x; 1.0067x over previous
#include <cuda_runtime.h>
#include <math.h>
#include <mma.h>

using namespace nvcuda;

// Problem constants
#define B_    256
#define P_    100
#define ENC_  1536
#define DEC_  512
#define ATT_  256
#define EMB_  256
#define V_    193
#define T_    150
#define T1_   151
#define N1_   1792   // att2(256) + f_beta(1536)
#define K2_   2048   // awe(1536) + h(512)
#define N2_   2048   // 4*DEC gate-interleaved

#define HP_BLOCKS 112          // hproj tiles in fused kernel 1
#define HPP_GRID (HP_BLOCKS + B_)

// Scratch (device globals: allocation-free per harness rules)
__device__ float g_h[B_ * DEC_];
__device__ float g_c[B_ * DEC_];
__device__ float g_mean[B_ * ENC_];
__device__ float g_att1[B_ * P_ * ATT_];
__device__ float g_hproj[B_ * N1_];
__device__ float g_x[B_ * K2_];          // [gated awe (1536) | h (512)]
__device__ float g_Wcat1[DEC_ * N1_];    // [W_dec_att | W_f_beta]
__device__ float g_bcat1[N1_];
__device__ float g_Wcat2[K2_ * N2_];     // rows: [W_ih_enc ; W_hh], cols interleaved d*4+g
__device__ float g_embW[V_ * N2_];       // emb@W_ih_emb + b_ih + b_hh, cols interleaved

__device__ __forceinline__ float sigmoidf_(float x) { return 1.0f / (1.0f + expf(-x)); }

__device__ __forceinline__ float tf32r(float x) {
    unsigned int u = __float_as_uint(x), v;
    asm("cvt.rna.tf32.f32 %0, %1;" : "=r"(v) : "r"(u));
    return __uint_as_float(v);
}
__device__ __forceinline__ float4 tf32r4(float4 v) {
    return make_float4(tf32r(v.x), tf32r(v.y), tf32r(v.z), tf32r(v.w));
}

typedef wmma::fragment<wmma::matrix_a, 16, 16, 8, wmma::precision::tf32, wmma::row_major> FragA;
typedef wmma::fragment<wmma::matrix_b, 16, 16, 8, wmma::precision::tf32, wmma::row_major> FragB;
typedef wmma::fragment<wmma::accumulator, 16, 16, 8, float> FragC;

// ---------------------------------------------------------------------------
// tf32 tensor-core 32x128 GEMM tile, BK=32, 256 threads = 8 warps (2 M x 4 N).
// ---------------------------------------------------------------------------
__device__ __forceinline__ void gemm_tc_tile(const float* __restrict__ A, int lda,
                                             const float* __restrict__ W, int N, int K,
                                             int rows0, int cols0,
                                             float (*As)[36], float (*Bs)[136],
                                             FragC& acc0, FragC& acc1,
                                             int warpM, int warpN) {
    const int tid  = threadIdx.x;
    const int arow = tid >> 3;           // 0..31
    const int acol = (tid & 7) << 2;     // 0..28
    const int brow = tid >> 5;           // 0..7 (+8r)
    const int bcol = (tid & 31) << 2;    // 0..124

    float4 aReg = *(const float4*)(A + (size_t)(rows0 + arow) * lda + acol);
    float4 bReg[4];
#pragma unroll
    for (int r = 0; r < 4; r++)
        bReg[r] = *(const float4*)(W + (size_t)(brow + 8 * r) * N + cols0 + bcol);

    for (int k0 = 0; k0 < K; k0 += 32) {
        *(float4*)&As[arow][acol] = tf32r4(aReg);
#pragma unroll
        for (int r = 0; r < 4; r++)
            *(float4*)&Bs[brow + 8 * r][bcol] = tf32r4(bReg[r]);
        __syncthreads();
        if (k0 + 32 < K) {
            aReg = *(const float4*)(A + (size_t)(rows0 + arow) * lda + k0 + 32 + acol);
#pragma unroll
            for (int r = 0; r < 4; r++)
                bReg[r] = *(const float4*)(W + (size_t)(k0 + 32 + brow + 8 * r) * N + cols0 + bcol);
        }
#pragma unroll
        for (int ks = 0; ks < 4; ks++) {
            FragA af;
            FragB bf0, bf1;
            wmma::load_matrix_sync(af, &As[warpM * 16][ks * 8], 36);
            wmma::load_matrix_sync(bf0, &Bs[ks * 8][warpN * 32], 136);
            wmma::load_matrix_sync(bf1, &Bs[ks * 8][warpN * 32 + 16], 136);
            wmma::mma_sync(acc0, af, bf0, acc0);
            wmma::mma_sync(acc1, af, bf1, acc1);
        }
        __syncthreads();
    }
}

// ---------------------------------------------------------------------------
// Fused kernel 1: blocks 0..111 compute hproj tiles (h @ Wcat1 + bcat1);
// blocks 112..367 compute preds for timestep t-1 (skipped at t==0).
// Both only read h (state after gates of t-1) -> dependency-clean in one launch.
// ---------------------------------------------------------------------------
__global__ void __launch_bounds__(256)
hproj_preds(const float* __restrict__ h, const float* __restrict__ Wcat1,
            const float* __restrict__ bcat1, float* __restrict__ hproj,
            const float* __restrict__ Wfc, const float* __restrict__ bfc,
            float* __restrict__ out, const int* __restrict__ len, int t) {
    __shared__ __align__(16) float As[32][36];
    __shared__ __align__(16) float Bs[32][136];
    __shared__ float hs[DEC_];

    const int blk = blockIdx.x;
    const int tid = threadIdx.x;

    if (blk < HP_BLOCKS) {
        // ---- hproj GEMM tile ----
        const int rows0 = (blk / 14) * 32;
        const int cols0 = (blk % 14) * 128;
        if (t >= len[rows0] - 1) return;
        const int warp = tid >> 5;
        const int warpM = warp >> 2, warpN = warp & 3;
        FragC acc0, acc1;
        wmma::fill_fragment(acc0, 0.0f);
        wmma::fill_fragment(acc1, 0.0f);
        gemm_tc_tile(h, DEC_, Wcat1, N1_, DEC_, rows0, cols0, As, Bs,
                     acc0, acc1, warpM, warpN);
        wmma::store_matrix_sync(&Bs[warpM * 16][warpN * 32], acc0, 136, wmma::mem_row_major);
        wmma::store_matrix_sync(&Bs[warpM * 16][warpN * 32 + 16], acc1, 136, wmma::mem_row_major);
        __syncthreads();
        const int r = tid >> 3;
        const int cb = (tid & 7) << 4;
#pragma unroll
        for (int u = 0; u < 4; u++) {
            const int col = cb + u * 4;
            float4 v = *(const float4*)&Bs[r][col];
            float4 bv = *(const float4*)(bcat1 + cols0 + col);
            v.x += bv.x; v.y += bv.y; v.z += bv.z; v.w += bv.w;
            *(float4*)(hproj + (size_t)(rows0 + r) * N1_ + cols0 + col) = v;
        }
    } else {
        // ---- preds for t-1 ----
        if (t == 0) return;
        const int b = blk - HP_BLOCKS;
        const int tp = t - 1;
        float* o = out + ((size_t)b * T_ + tp) * V_;
        if (tp >= len[b] - 1) {
            if (tid < V_) o[tid] = 0.0f;
            return;
        }
        hs[tid] = h[(size_t)b * DEC_ + tid];
        hs[tid + 256] = h[(size_t)b * DEC_ + tid + 256];
        __syncthreads();
        if (tid < V_) {
            float acc = bfc[tid];
#pragma unroll 8
            for (int k = 0; k < DEC_; k++) acc += hs[k] * Wfc[(size_t)k * V_ + tid];
            o[tid] = acc;
        }
    }
}

// ---------------------------------------------------------------------------
// Fused attention: one block (512 threads) per batch element.
// scores = relu(att1 + att2).Wfull -> softmax over P -> gated awe into
// x[:,0:1536], plus h copy into x[:,1536:2048]. Removes the alpha round-trip
// and one dependent launch from the per-step chain.
// ---------------------------------------------------------------------------
__global__ void __launch_bounds__(512)
attn_fused(const float* __restrict__ enc, const float* __restrict__ att1,
           const float* __restrict__ Wfull, const float* __restrict__ hproj,
           const float* __restrict__ h, float* __restrict__ x,
           const int* __restrict__ len, int t) {
    const int b = blockIdx.x;
    if (t >= len[b] - 1) return;
    const int tid = threadIdx.x;
    const int warp = tid >> 5, lane = tid & 31;

    __shared__ float att2s[ATT_];
    __shared__ float wf[ATT_];
    __shared__ float es[P_ + 4];

    if (tid < ATT_) {
        att2s[tid] = hproj[(size_t)b * N1_ + tid];
        wf[tid] = Wfull[tid];
    }
    __syncthreads();

    // scores: 16 warps cover P=100 in 7 rounds
    for (int p = warp; p < P_; p += 16) {
        const float* a1 = att1 + ((size_t)(b * P_ + p)) * ATT_;
        float part = 0.0f;
#pragma unroll 4
        for (int j = lane; j < ATT_; j += 32)
            part += fmaxf(a1[j] + att2s[j], 0.0f) * wf[j];
#pragma unroll
        for (int o = 16; o; o >>= 1) part += __shfl_xor_sync(0xffffffffu, part, o);
        if (lane == 0) es[p] = part;
    }
    __syncthreads();

    // softmax over P (warp 0)
    if (tid < 32) {
        float m = -1e30f;
        for (int p = tid; p < P_; p += 32) m = fmaxf(m, es[p]);
#pragma unroll
        for (int o = 16; o; o >>= 1) m = fmaxf(m, __shfl_xor_sync(0xffffffffu, m, o));
        float s = 0.0f;
        for (int p = tid; p < P_; p += 32) {
            float ex = expf(es[p] - m);
            es[p] = ex;
            s += ex;
        }
#pragma unroll
        for (int o = 16; o; o >>= 1) s += __shfl_xor_sync(0xffffffffu, s, o);
        float inv = 1.0f / s;
        for (int p = tid; p < P_; p += 32) es[p] *= inv;
    }
    __syncthreads();

    // h copy into x's recurrent slice (one element per thread)
    x[(size_t)b * K2_ + 1536 + tid] = h[(size_t)b * DEC_ + tid];

    // gated awe: 384 float4 lanes cover ENC=1536
    if (tid < ENC_ / 4) {
        const float4* ep = (const float4*)(enc + ((size_t)b * P_) * ENC_);
        float4 acc = make_float4(0.f, 0.f, 0.f, 0.f);
#pragma unroll 4
        for (int p = 0; p < P_; p++) {
            float4 v = ep[(size_t)p * (ENC_ / 4) + tid];
            float a = es[p];
            acc.x += a * v.x; acc.y += a * v.y; acc.z += a * v.z; acc.w += a * v.w;
        }
        const int col = tid * 4;
        float4 gl = *(const float4*)(hproj + (size_t)b * N1_ + ATT_ + col);
        float4 o;
        o.x = acc.x * sigmoidf_(gl.x);
        o.y = acc.y * sigmoidf_(gl.y);
        o.z = acc.z * sigmoidf_(gl.z);
        o.w = acc.w * sigmoidf_(gl.w);
        *(float4*)(x + (size_t)b * K2_ + col) = o;
    }
}

// ---------------------------------------------------------------------------
// Fused gates GEMM (tf32) + LSTM cell.
// ---------------------------------------------------------------------------
__global__ void __launch_bounds__(256)
gates_tc(const float* __restrict__ x, const float* __restrict__ W,
         const float* __restrict__ embW, const int* __restrict__ caps,
         float* __restrict__ h, float* __restrict__ c,
         const int* __restrict__ len, int t) {
    __shared__ __align__(16) float As[32][36];
    __shared__ __align__(16) float Bs[32][136];
    const int rows0 = blockIdx.y * 32;
    if (t >= len[rows0] - 1) return;
    const int cols0 = blockIdx.x * 128;
    const int warp = threadIdx.x >> 5;
    const int warpM = warp >> 2, warpN = warp & 3;

    FragC acc0, acc1;
    wmma::fill_fragment(acc0, 0.0f);
    wmma::fill_fragment(acc1, 0.0f);
    gemm_tc_tile(x, K2_, W, N2_, K2_, rows0, cols0, As, Bs, acc0, acc1, warpM, warpN);

    wmma::store_matrix_sync(&Bs[warpM * 16][warpN * 32], acc0, 136, wmma::mem_row_major);
    wmma::store_matrix_sync(&Bs[warpM * 16][warpN * 32 + 16], acc1, 136, wmma::mem_row_major);
    __syncthreads();

    const int tid = threadIdx.x;
    const int r = tid >> 3;
    const int cb = (tid & 7) << 4;
    const int b = rows0 + r;
    if (t >= len[b] - 1) return;
    const int token = caps[b * T1_ + t];

#pragma unroll
    for (int uu = 0; uu < 4; uu++) {
        const int cp = cols0 + cb + uu * 4;
        const int d = cp >> 2;
        float4 gv = *(const float4*)&Bs[r][cb + uu * 4];
        float4 ew = *(const float4*)(embW + (size_t)token * N2_ + cp);
        float vi = gv.x + ew.x;
        float vf = gv.y + ew.y;
        float vg = gv.z + ew.z;
        float vo = gv.w + ew.w;
        float c_old = c[(size_t)b * DEC_ + d];
        float ii = sigmoidf_(vi);
        float ff = sigmoidf_(vf);
        float gg = tanhf(vg);
        float oo = sigmoidf_(vo);
        float cn = ff * c_old + ii * gg;
        float hn = oo * tanhf(cn);
        c[(size_t)b * DEC_ + d] = cn;
        h[(size_t)b * DEC_ + d] = hn;
    }
}

// ---------------------------------------------------------------------------
// preds[b,t,:] = active ? h[b,:] @ W_fc + b_fc : 0   (final-step flush)
// ---------------------------------------------------------------------------
__global__ void preds_kernel(const float* __restrict__ Wfc, const float* __restrict__ bfc,
                             const float* __restrict__ h, float* __restrict__ out,
                             const int* __restrict__ len, int t) {
    const int b = blockIdx.x;
    const int tid = threadIdx.x;
    float* o = out + ((size_t)b * T_ + t) * V_;
    if (t >= len[b] - 1) {
        if (tid < V_) o[tid] = 0.0f;
        return;
    }
    __shared__ float hs[DEC_];
    hs[tid] = h[(size_t)b * DEC_ + tid];
    hs[tid + 256] = h[(size_t)b * DEC_ + tid + 256];
    __syncthreads();
    if (tid < V_) {
        float acc = bfc[tid];
#pragma unroll 8
        for (int k = 0; k < DEC_; k++) acc += hs[k] * Wfc[(size_t)k * V_ + tid];
        o[tid] = acc;
    }
}

// ---------------------------------------------------------------------------
// Standalone tf32 GEMM for precompute (h0, c0, att1)
// ---------------------------------------------------------------------------
__global__ void __launch_bounds__(256)
gemm_tc(const float* __restrict__ A, int lda,
        const float* __restrict__ W, int N, int K,
        const float* __restrict__ bias, float* __restrict__ C) {
    __shared__ __align__(16) float As[32][36];
    __shared__ __align__(16) float Bs[32][136];
    const int rows0 = blockIdx.y * 32;
    const int cols0 = blockIdx.x * 128;
    const int warp = threadIdx.x >> 5;
    const int warpM = warp >> 2, warpN = warp & 3;

    FragC acc0, acc1;
    wmma::fill_fragment(acc0, 0.0f);
    wmma::fill_fragment(acc1, 0.0f);
    gemm_tc_tile(A, lda, W, N, K, rows0, cols0, As, Bs, acc0, acc1, warpM, warpN);

    wmma::store_matrix_sync(&Bs[warpM * 16][warpN * 32], acc0, 136, wmma::mem_row_major);
    wmma::store_matrix_sync(&Bs[warpM * 16][warpN * 32 + 16], acc1, 136, wmma::mem_row_major);
    __syncthreads();

    const int tid = threadIdx.x;
    const int r = tid >> 3;
    const int cb = (tid & 7) << 4;
#pragma unroll
    for (int u = 0; u < 4; u++) {
        const int col = cb + u * 4;
        float4 v = *(const float4*)&Bs[r][col];
        float4 bv = *(const float4*)(bias + cols0 + col);
        v.x += bv.x; v.y += bv.y; v.z += bv.z; v.w += bv.w;
        *(float4*)(C + (size_t)(rows0 + r) * N + cols0 + col) = v;
    }
}

// ---------------------------------------------------------------------------
// Precompute kernels
// ---------------------------------------------------------------------------
__global__ void mean_kernel(const float* __restrict__ enc, float* __restrict__ mean) {
    const int b = blockIdx.y;
    const int e = blockIdx.x * 256 + threadIdx.x;
    const float* ep = enc + ((size_t)b * P_) * ENC_ + e;
    float s = 0.0f;
#pragma unroll 4
    for (int p = 0; p < P_; p++) s += ep[(size_t)p * ENC_];
    mean[(size_t)b * ENC_ + e] = s * (1.0f / P_);
}

__global__ void wcat1_kernel(const float* __restrict__ Wda, const float* __restrict__ Wfb,
                             const float* __restrict__ bda, const float* __restrict__ bfb,
                             float* __restrict__ Wc, float* __restrict__ bc) {
    int idx = blockIdx.x * 256 + threadIdx.x;
    if (idx >= DEC_ * N1_) return;
    int k = idx / N1_, n = idx % N1_;
    Wc[idx] = (n < ATT_) ? Wda[k * ATT_ + n] : Wfb[k * ENC_ + (n - ATT_)];
    if (k == 0) bc[n] = (n < ATT_) ? bda[n] : bfb[n - ATT_];
}

__global__ void wcat2_kernel(const float* __restrict__ Wih, const float* __restrict__ Whh,
                             float* __restrict__ Wc) {
    int idx = blockIdx.x * 256 + threadIdx.x;
    if (idx >= K2_ * N2_) return;
    int k = idx / N2_, cp = idx % N2_;
    int dd = cp >> 2, g = cp & 3;
    int oc = g * DEC_ + dd;
    Wc[idx] = (k < 1536) ? Wih[(size_t)(256 + k) * N2_ + oc]
                         : Whh[(size_t)(k - 1536) * N2_ + oc];
}

// embW[v, d*4+g] = sum_k emb[v,k] * W_ih[k, g*512+d] + b_ih + b_hh
__global__ void embw_kernel(const float* __restrict__ emb, const float* __restrict__ Wih,
                            const float* __restrict__ bih, const float* __restrict__ bhh,
                            float* __restrict__ out) {
    const int oc = blockIdx.x * 256 + threadIdx.x;   // 0..2047
    const int v0 = blockIdx.y * 8;
    __shared__ float er[8][EMB_];
#pragma unroll
    for (int r = 0; r < 8; r++) {
        int v = v0 + r;
        er[r][threadIdx.x] = (v < V_) ? emb[(size_t)v * EMB_ + threadIdx.x] : 0.0f;
    }
    __syncthreads();
    float base = bih[oc] + bhh[oc];
    float acc[8];
#pragma unroll
    for (int r = 0; r < 8; r++) acc[r] = base;
    for (int k = 0; k < EMB_; k++) {
        float w = Wih[(size_t)k * N2_ + oc];
#pragma unroll
        for (int r = 0; r < 8; r++) acc[r] += er[r][k] * w;
    }
    const int dd = oc & (DEC_ - 1);
    const int g = oc >> 9;
#pragma unroll
    for (int r = 0; r < 8; r++) {
        int v = v0 + r;
        if (v < V_) out[(size_t)v * N2_ + dd * 4 + g] = acc[r];
    }
}

// ---------------------------------------------------------------------------
extern "C" void kernel_launch(void* const* d_in, const int* in_sizes, int n_in,
                              void* d_out, int out_size) {
    const float* enc        = (const float*)d_in[0];
    const int*   caps       = (const int*)d_in[1];
    const int*   lens       = (const int*)d_in[2];
    const float* emb        = (const float*)d_in[3];
    const float* W_enc_att  = (const float*)d_in[4];
    const float* b_enc_att  = (const float*)d_in[5];
    const float* W_dec_att  = (const float*)d_in[6];
    const float* b_dec_att  = (const float*)d_in[7];
    const float* W_full_att = (const float*)d_in[8];
    // d_in[9] = b_full_att (softmax-invariant; unused)
    const float* W_init_h   = (const float*)d_in[10];
    const float* b_init_h   = (const float*)d_in[11];
    const float* W_init_c   = (const float*)d_in[12];
    const float* b_init_c   = (const float*)d_in[13];
    const float* W_f_beta   = (const float*)d_in[14];
    const float* b_f_beta   = (const float*)d_in[15];
    const float* W_ih       = (const float*)d_in[16];
    const float* b_ih       = (const float*)d_in[17];
    const float* W_hh       = (const float*)d_in[18];
    const float* b_hh       = (const float*)d_in[19];
    const float* W_fc       = (const float*)d_in[20];
    const float* b_fc       = (const float*)d_in[21];
    float* out = (float*)d_out;

    float *ph, *pc, *pmean, *patt1, *phproj, *px, *pWcat1, *pbcat1, *pWcat2, *pembW;
    cudaGetSymbolAddress((void**)&ph,     g_h);
    cudaGetSymbolAddress((void**)&pc,     g_c);
    cudaGetSymbolAddress((void**)&pmean,  g_mean);
    cudaGetSymbolAddress((void**)&patt1,  g_att1);
    cudaGetSymbolAddress((void**)&phproj, g_hproj);
    cudaGetSymbolAddress((void**)&px,     g_x);
    cudaGetSymbolAddress((void**)&pWcat1, g_Wcat1);
    cudaGetSymbolAddress((void**)&pbcat1, g_bcat1);
    cudaGetSymbolAddress((void**)&pWcat2, g_Wcat2);
    cudaGetSymbolAddress((void**)&pembW,  g_embW);

    // ---- precompute ----
    mean_kernel<<<dim3(ENC_ / 256, B_), 256>>>(enc, pmean);
    wcat1_kernel<<<(DEC_ * N1_ + 255) / 256, 256>>>(W_dec_att, W_f_beta, b_dec_att, b_f_beta,
                                                    pWcat1, pbcat1);
    wcat2_kernel<<<(K2_ * N2_ + 255) / 256, 256>>>(W_ih, W_hh, pWcat2);
    embw_kernel<<<dim3(N2_ / 256, (V_ + 7) / 8), 256>>>(emb, W_ih, b_ih, b_hh, pembW);
    // h0, c0
    gemm_tc<<<dim3(DEC_ / 128, B_ / 32), 256>>>(pmean, ENC_, W_init_h, DEC_, ENC_,
                                                b_init_h, ph);
    gemm_tc<<<dim3(DEC_ / 128, B_ / 32), 256>>>(pmean, ENC_, W_init_c, DEC_, ENC_,
                                                b_init_c, pc);
    // att1 = encoder_out @ W_enc_att + b (M = B*P = 25600)
    gemm_tc<<<dim3(ATT_ / 128, (B_ * P_) / 32), 256>>>(enc, ENC_, W_enc_att, ATT_, ENC_,
                                                       b_enc_att, patt1);

    // ---- timestep loop: 3 launches/step ----
    for (int t = 0; t < T_; t++) {
        hproj_preds<<<HPP_GRID, 256>>>(ph, pWcat1, pbcat1, phproj, W_fc, b_fc, out, lens, t);
        attn_fused<<<B_, 512>>>(enc, patt1, W_full_att, phproj, ph, px, lens, t);
        gates_tc<<<dim3(N2_ / 128, B_ / 32), 256>>>(px, pWcat2, pembW, caps, ph, pc,
                                                    lens, t);
    }
    // final preds flush
    preds_kernel<<<B_, 256>>>(W_fc, b_fc, ph, out, lens, T_ - 1);
}